// round 4
// baseline (speedup 1.0000x reference)
#include <cuda_runtime.h>

#define FULLMASK 0xffffffffu

// ---------------------------------------------------------------------------
// 9-qubit statevector, 512 complex amps distributed as:
//   amp index i = lane*16 + r  (lane: bits 8..4, r: bits 3..0)
// Qubit q lives at bit position (8-q) of i  (row-major (2,)*9 state).
// RX(theta) = [[c, -i*s], [-i*s, c]],  c=cos(t/2), s=sin(t/2)  (symmetric)
//   new_amp = c*a + (-i*s)*partner:  nx = c*ax + s*py ; ny = c*ay - s*px
// ---------------------------------------------------------------------------

template<int M>  // RX on a register bit (bitpos 0..3), M = 1<<bitpos
__device__ __forceinline__ void rx_regbit(float2 (&a)[16], float c, float s) {
#pragma unroll
    for (int r = 0; r < 16; ++r) {
        if ((r & M) == 0) {
            const int r1 = r | M;
            float2 a0 = a[r], a1 = a[r1];
            a[r].x  = c * a0.x + s * a1.y;
            a[r].y  = c * a0.y - s * a1.x;
            a[r1].x = c * a1.x + s * a0.y;
            a[r1].y = c * a1.y - s * a0.x;
        }
    }
}

template<int LM> // RX on a lane bit (bitpos 4..8), LM = 1<<(bitpos-4)
__device__ __forceinline__ void rx_lanebit(float2 (&a)[16], float c, float s) {
#pragma unroll
    for (int r = 0; r < 16; ++r) {
        float px = __shfl_xor_sync(FULLMASK, a[r].x, LM);
        float py = __shfl_xor_sync(FULLMASK, a[r].y, LM);
        a[r].x = c * a[r].x + s * py;
        a[r].y = c * a[r].y - s * px;
    }
}

template<int BP>
__device__ __forceinline__ void rx(float2 (&a)[16], float c, float s) {
    if constexpr (BP >= 4) rx_lanebit<(1 << (BP - 4))>(a, c, s);
    else                   rx_regbit<(1 << BP)>(a, c, s);
}

// CNOT: for indices with control bit == 1, flip target bit (amp permutation).

template<int CM, int TM> // control + target both lane bits
__device__ __forceinline__ void cnot_ll(float2 (&a)[16], int lane) {
#pragma unroll
    for (int r = 0; r < 16; ++r) {
        float tx = __shfl_xor_sync(FULLMASK, a[r].x, TM);
        float ty = __shfl_xor_sync(FULLMASK, a[r].y, TM);
        if (lane & CM) { a[r].x = tx; a[r].y = ty; }
    }
}

template<int CM, int M>  // control lane bit, target register bit
__device__ __forceinline__ void cnot_lr(float2 (&a)[16], int lane) {
    if (lane & CM) {
#pragma unroll
        for (int r = 0; r < 16; ++r)
            if ((r & M) == 0) { float2 t = a[r]; a[r] = a[r | M]; a[r | M] = t; }
    }
}

template<int CM, int TM> // control + target both register bits
__device__ __forceinline__ void cnot_rr(float2 (&a)[16]) {
#pragma unroll
    for (int r = 0; r < 16; ++r)
        if ((r & CM) && !(r & TM)) { float2 t = a[r]; a[r] = a[r | TM]; a[r | TM] = t; }
}

template<int CM, int TM> // control register bit, target lane bit
__device__ __forceinline__ void cnot_rl(float2 (&a)[16]) {
#pragma unroll
    for (int r = 0; r < 16; ++r) {
        if (r & CM) {   // compile-time uniform after unroll -> shfl is safe
            a[r].x = __shfl_xor_sync(FULLMASK, a[r].x, TM);
            a[r].y = __shfl_xor_sync(FULLMASK, a[r].y, TM);
        }
    }
}

__global__ void __launch_bounds__(128)
quanv_kernel(const float* __restrict__ x,   // (4,3,28,28)
             const float* __restrict__ w,   // (2,9)
             float* __restrict__ out)       // (4,4,26,26)
{
    const int lane = threadIdx.x & 31;
    const int g = blockIdx.x * (blockDim.x >> 5) + (threadIdx.x >> 5); // [0,2704)
    const int b = g / 676;
    int rem = g - b * 676;
    const int oy = rem / 26;
    const int ox = rem - oy * 26;

    // trainable-weight angles: trig once per thread
    float cw[18], sw[18];
#pragma unroll
    for (int i = 0; i < 18; ++i) __sincosf(0.5f * w[i], &sw[i], &cw[i]);

    float zacc0 = 0.f, zacc1 = 0.f, zacc2 = 0.f, zacc3 = 0.f;

    for (int ch = 0; ch < 3; ++ch) {
        // 3x3 patch angles (uniform across warp -> L1 broadcast)
        float cp[9], sp[9];
#pragma unroll
        for (int dy = 0; dy < 3; ++dy)
#pragma unroll
            for (int dx = 0; dx < 3; ++dx) {
                float v = x[((b * 3 + ch) * 28 + (oy + dy)) * 28 + (ox + dx)];
                __sincosf(0.5f * v, &sp[dy * 3 + dx], &cp[dy * 3 + dx]);
            }

        // |0...0> : amp index 0 = (lane 0, r 0)
        float2 a[16];
#pragma unroll
        for (int r = 0; r < 16; ++r) a[r] = make_float2(0.f, 0.f);
        if (lane == 0) a[0].x = 1.f;

        // AngleEmbedding: RX(p_q) on qubit q (bitpos 8-q)
        rx<8>(a, cp[0], sp[0]);
        rx<7>(a, cp[1], sp[1]);
        rx<6>(a, cp[2], sp[2]);
        rx<5>(a, cp[3], sp[3]);
        rx<4>(a, cp[4], sp[4]);
        rx<3>(a, cp[5], sp[5]);
        rx<2>(a, cp[6], sp[6]);
        rx<1>(a, cp[7], sp[7]);
        rx<0>(a, cp[8], sp[8]);

        // BasicEntanglerLayers: per layer, RX on every qubit then CNOT ring
#pragma unroll
        for (int l = 0; l < 2; ++l) {
            const int o = l * 9;
            rx<8>(a, cw[o + 0], sw[o + 0]);
            rx<7>(a, cw[o + 1], sw[o + 1]);
            rx<6>(a, cw[o + 2], sw[o + 2]);
            rx<5>(a, cw[o + 3], sw[o + 3]);
            rx<4>(a, cw[o + 4], sw[o + 4]);
            rx<3>(a, cw[o + 5], sw[o + 5]);
            rx<2>(a, cw[o + 6], sw[o + 6]);
            rx<1>(a, cw[o + 7], sw[o + 7]);
            rx<0>(a, cw[o + 8], sw[o + 8]);

            // CNOT(q, q+1 mod 9) for q = 0..8; (ctrl_bp, tgt_bp):
            cnot_ll<16, 8>(a, lane);  // (8,7)
            cnot_ll< 8, 4>(a, lane);  // (7,6)
            cnot_ll< 4, 2>(a, lane);  // (6,5)
            cnot_ll< 2, 1>(a, lane);  // (5,4)
            cnot_lr< 1, 8>(a, lane);  // (4,3)
            cnot_rr< 8, 4>(a);        // (3,2)
            cnot_rr< 4, 2>(a);        // (2,1)
            cnot_rr< 2, 1>(a);        // (1,0)
            cnot_rl< 1,16>(a);        // (0,8)
        }

        // per-lane probability mass
        float s = 0.f;
#pragma unroll
        for (int r = 0; r < 16; ++r) s += a[r].x * a[r].x + a[r].y * a[r].y;

        // <Z_f> for f=0..3: sign from lane bit (4-f); butterfly sum
#pragma unroll
        for (int f = 0; f < 4; ++f) {
            float v = (lane & (16 >> f)) ? -s : s;
#pragma unroll
            for (int off = 16; off >= 1; off >>= 1)
                v += __shfl_xor_sync(FULLMASK, v, off);
            if (f == 0) zacc0 += v;
            else if (f == 1) zacc1 += v;
            else if (f == 2) zacc2 += v;
            else zacc3 += v;
        }
    }

    if (lane == 0) {
        const float inv3 = 1.0f / 3.0f;
        out[((b * 4 + 0) * 26 + oy) * 26 + ox] = zacc0 * inv3;
        out[((b * 4 + 1) * 26 + oy) * 26 + ox] = zacc1 * inv3;
        out[((b * 4 + 2) * 26 + oy) * 26 + ox] = zacc2 * inv3;
        out[((b * 4 + 3) * 26 + oy) * 26 + ox] = zacc3 * inv3;
    }
}

extern "C" void kernel_launch(void* const* d_in, const int* in_sizes, int n_in,
                              void* d_out, int out_size) {
    const float* x = (const float*)d_in[0];   // (4,3,28,28) f32
    const float* w = (const float*)d_in[1];   // (2,9) f32
    float* out = (float*)d_out;               // (4,4,26,26) f32
    // 2704 warps = 676 blocks x 4 warps; one warp per (b, oy, ox)
    quanv_kernel<<<676, 128>>>(x, w, out);
}

// round 5
// speedup vs baseline: 2.1102x; 2.1102x over previous
#include <cuda_runtime.h>

#define FULLMASK 0xffffffffu

__device__ __forceinline__ float shx(float v, int m) {
    return __shfl_xor_sync(FULLMASK, v, m);
}

// ---------------------------------------------------------------------------
// 9-qubit statevector phi in the CNOT-conjugated frame.
// amp index i = lane*16 + r (lane = i bits 8..4, r = i bits 3..0).
// Qubit q lives at bit position (8-q).
// Generalized RX pairing i <-> i^mask, matrix [[c,-is],[-is,c]] (symmetric):
//   new.x = c*a.x + s*p.y ; new.y = c*a.y - s*p.x   (p = partner amp)
// ---------------------------------------------------------------------------

template<int MR>   // register-only mask
__device__ __forceinline__ void rx_reg(float2 (&a)[16], float c, float s) {
    constexpr int HB = (MR & 8) ? 8 : (MR & 4) ? 4 : (MR & 2) ? 2 : 1;
#pragma unroll
    for (int r = 0; r < 16; ++r) {
        if (!(r & HB)) {
            const int r1 = r ^ MR;
            float2 a0 = a[r], a1 = a[r1];
            a[r].x  = c * a0.x + s * a1.y;
            a[r].y  = c * a0.y - s * a1.x;
            a[r1].x = c * a1.x + s * a0.y;
            a[r1].y = c * a1.y - s * a0.x;
        }
    }
}

template<int ML, int MR>  // lane mask ML != 0, optional register mask MR
__device__ __forceinline__ void rx_lane(float2 (&a)[16], float c, float s) {
    if constexpr (MR == 0) {
#pragma unroll
        for (int r = 0; r < 16; ++r) {
            float px = shx(a[r].x, ML);
            float py = shx(a[r].y, ML);
            a[r].x = c * a[r].x + s * py;
            a[r].y = c * a[r].y - s * px;
        }
    } else {
        constexpr int HB = (MR & 8) ? 8 : (MR & 4) ? 4 : (MR & 2) ? 2 : 1;
#pragma unroll
        for (int r = 0; r < 16; ++r) {
            if (!(r & HB)) {
                const int r1 = r ^ MR;
                // read both partners (lockstep, pre-update) then write both
                float p0x = shx(a[r1].x, ML), p0y = shx(a[r1].y, ML);
                float p1x = shx(a[r].x,  ML), p1y = shx(a[r].y,  ML);
                a[r].x  = c * a[r].x  + s * p0y;
                a[r].y  = c * a[r].y  - s * p0x;
                a[r1].x = c * a[r1].x + s * p1y;
                a[r1].y = c * a[r1].y - s * p1x;
            }
        }
    }
}

__global__ void __launch_bounds__(128)
quanv_kernel(const float* __restrict__ x,   // (4,3,28,28)
             const float* __restrict__ w,   // (2,9)
             float* __restrict__ out)       // (4,4,26,26)
{
    // layer-2 weight trig: channel-invariant, shared per block
    __shared__ float cw1[9], sw1[9];
    if (threadIdx.x < 9)
        __sincosf(0.5f * w[9 + threadIdx.x], &sw1[threadIdx.x], &cw1[threadIdx.x]);
    __syncthreads();

    const int lane = threadIdx.x & 31;
    const int g = blockIdx.x * 4 + (threadIdx.x >> 5);   // [0,2704)
    const int b = g / 676;
    int rem = g - b * 676;
    const int oy = rem / 26;
    const int ox = rem - oy * 26;

    // measurement lane signs: parity(lane & laneMask(row_{p_f}(M^2)))
    const float sg0 = (__popc(lane & 0x05) & 1) ? -1.f : 1.f;  // row 0x055
    const float sg1 = (__popc(lane & 0x17) & 1) ? -1.f : 1.f;  // row 0x17F
    const float sg2 = (__popc(lane & 0x0B) & 1) ? -1.f : 1.f;  // row 0x0BF
    const float sg3 = (__popc(lane & 0x15) & 1) ? -1.f : 1.f;  // row 0x15F

    // (-i)^popc(lane) for product-state init
    const int lk = __popc(lane) & 3;
    const float wx = (lk == 0) ? 1.f : (lk == 2) ? -1.f : 0.f;
    const float wy = (lk == 3) ? 1.f : (lk == 1) ? -1.f : 0.f;

    float sAsum = 0.f, sBsum = 0.f;

    for (int ch = 0; ch < 3; ++ch) {
        // fused angles theta_q = patch[q] + w0[q]  (RX(a)RX(b)=RX(a+b))
        const float* xp = x + ((b * 3 + ch) * 28 + oy) * 28 + ox;
        float cq[9], sq[9];
#pragma unroll
        for (int q = 0; q < 9; ++q) {
            float v = xp[(q / 3) * 28 + (q % 3)] + w[q];
            __sincosf(0.5f * v, &sq[q], &cq[q]);
        }

        // product state: amp(i) = prod_q (bit ? -i*s_q : c_q)
        // lane bit 4..0 = qubit 0..4 ; r bit 3..0 = qubit 5..8
        const float laneMag = ((lane & 16) ? sq[0] : cq[0])
                            * ((lane &  8) ? sq[1] : cq[1])
                            * ((lane &  4) ? sq[2] : cq[2])
                            * ((lane &  2) ? sq[3] : cq[3])
                            * ((lane &  1) ? sq[4] : cq[4]);
        float hi[4], lo[4];
        hi[0] = cq[5] * cq[6];  hi[1] = cq[5] * sq[6];
        hi[2] = sq[5] * cq[6];  hi[3] = sq[5] * sq[6];
        lo[0] = cq[7] * cq[8];  lo[1] = cq[7] * sq[8];
        lo[2] = sq[7] * cq[8];  lo[3] = sq[7] * sq[8];

        float2 a[16];
#pragma unroll
        for (int r = 0; r < 16; ++r) {
            float m = laneMag * hi[r >> 2] * lo[r & 3];
            const int k = __popc(r) & 3;   // compile-time after unroll
            float ux = (k == 0) ? wx : (k == 1) ?  wy : (k == 2) ? -wx : -wy;
            float uy = (k == 0) ? wy : (k == 1) ? -wx : (k == 2) ? -wy :  wx;
            a[r].x = m * ux;
            a[r].y = m * uy;
        }

        // layer-2 RX in the conjugated frame: masks = M^{-1} e_{8-q}
        rx_lane<0x18, 0>(a, cw1[0], sw1[0]);  // q0
        rx_lane<0x0C, 0>(a, cw1[1], sw1[1]);  // q1
        rx_lane<0x06, 0>(a, cw1[2], sw1[2]);  // q2
        rx_lane<0x03, 0>(a, cw1[3], sw1[3]);  // q3
        rx_lane<0x01, 8>(a, cw1[4], sw1[4]);  // q4
        rx_reg <0x0C   >(a, cw1[5], sw1[5]);  // q5
        rx_reg <0x06   >(a, cw1[6], sw1[6]);  // q6
        rx_reg <0x03   >(a, cw1[7], sw1[7]);  // q7
        rx_lane<0x18, 1>(a, cw1[8], sw1[8]);  // q8

        // measurement partial sums (signs via rows of M^2; f=1..3 share parity(r))
        float sA = 0.f, sB = 0.f;
#pragma unroll
        for (int r = 0; r < 16; ++r) {
            float p = a[r].x * a[r].x + a[r].y * a[r].y;
            sA += (__popc(r & 5) & 1) ? -p : p;
            sB += (__popc(r)     & 1) ? -p : p;
        }
        sAsum += sA;
        sBsum += sB;
    }

    float z0 = sg0 * sAsum;
    float z1 = sg1 * sBsum;
    float z2 = sg2 * sBsum;
    float z3 = sg3 * sBsum;
#pragma unroll
    for (int off = 16; off >= 1; off >>= 1) {
        z0 += shx(z0, off);
        z1 += shx(z1, off);
        z2 += shx(z2, off);
        z3 += shx(z3, off);
    }

    if (lane == 0) {
        const float inv3 = 1.0f / 3.0f;
        out[((b * 4 + 0) * 26 + oy) * 26 + ox] = z0 * inv3;
        out[((b * 4 + 1) * 26 + oy) * 26 + ox] = z1 * inv3;
        out[((b * 4 + 2) * 26 + oy) * 26 + ox] = z2 * inv3;
        out[((b * 4 + 3) * 26 + oy) * 26 + ox] = z3 * inv3;
    }
}

extern "C" void kernel_launch(void* const* d_in, const int* in_sizes, int n_in,
                              void* d_out, int out_size) {
    const float* x = (const float*)d_in[0];   // (4,3,28,28) f32
    const float* w = (const float*)d_in[1];   // (2,9) f32
    float* out = (float*)d_out;               // (4,4,26,26) f32
    quanv_kernel<<<676, 128>>>(x, w, out);
}